// round 7
// baseline (speedup 1.0000x reference)
#include <cuda_runtime.h>
#include <cuda_bf16.h>
#include <cstdint>

// Problem constants: N=100000, E=3200000, DIN=128, H=256, M=500, O=100
#define NN  100000
#define EE  3200000
#define DIN 128
#define HH  256
#define MM  500
#define MP  512
#define OO  100

#define SCAN_B 1024
#define NBLK ((NN + SCAN_B - 1) / SCAN_B)   // 98

// ---- scratch (static device globals; referenced ONLY from device code) ----
__device__ int   g_deg[NN];
__device__ int   g_off[NN];
__device__ int   g_cur[NN];
__device__ int   g_bsum[128];
__device__ int   g_src[EE];
__device__ float g_dinv[NN];
__device__ __align__(16) float g_xagg[NN * DIN];   // 51.2 MB
__device__ __align__(16) float g_h   [NN * HH];    // 102.4 MB
__device__ __align__(16) float g_hagg[NN * HH];    // 102.4 MB
__device__ __align__(16) float g_p   [NN * MP];    // 204.8 MB
// transposed/split weights (bf16), [Npad][Kpad], k contiguous
__device__ __align__(16) __nv_bfloat16 g_w1t_hi[HH * DIN];
__device__ __align__(16) __nv_bfloat16 g_w1t_lo[HH * DIN];
__device__ __align__(16) __nv_bfloat16 g_w2t_hi[MP * HH];
__device__ __align__(16) __nv_bfloat16 g_w2t_lo[MP * HH];
__device__ __align__(16) __nv_bfloat16 g_wot_hi[128 * MP];
__device__ __align__(16) __nv_bfloat16 g_wot_lo[128 * MP];

// ============================ helpers ============================
__device__ __forceinline__ void split4(float4 v, uint64_t& hi, uint64_t& lo) {
    __nv_bfloat16 h0 = __float2bfloat16_rn(v.x), h1 = __float2bfloat16_rn(v.y);
    __nv_bfloat16 h2 = __float2bfloat16_rn(v.z), h3 = __float2bfloat16_rn(v.w);
    __nv_bfloat16 l0 = __float2bfloat16_rn(v.x - __bfloat162float(h0));
    __nv_bfloat16 l1 = __float2bfloat16_rn(v.y - __bfloat162float(h1));
    __nv_bfloat16 l2 = __float2bfloat16_rn(v.z - __bfloat162float(h2));
    __nv_bfloat16 l3 = __float2bfloat16_rn(v.w - __bfloat162float(h3));
    hi = (uint64_t)__bfloat16_as_ushort(h0) | ((uint64_t)__bfloat16_as_ushort(h1) << 16)
       | ((uint64_t)__bfloat16_as_ushort(h2) << 32) | ((uint64_t)__bfloat16_as_ushort(h3) << 48);
    lo = (uint64_t)__bfloat16_as_ushort(l0) | ((uint64_t)__bfloat16_as_ushort(l1) << 16)
       | ((uint64_t)__bfloat16_as_ushort(l2) << 32) | ((uint64_t)__bfloat16_as_ushort(l3) << 48);
}

__device__ __forceinline__ void mma16816(float* c, const uint32_t* a, const uint32_t* b) {
    asm volatile("mma.sync.aligned.m16n8k16.row.col.f32.bf16.bf16.f32 "
                 "{%0,%1,%2,%3}, {%4,%5,%6,%7}, {%8,%9}, {%0,%1,%2,%3};"
                 : "+f"(c[0]), "+f"(c[1]), "+f"(c[2]), "+f"(c[3])
                 : "r"(a[0]), "r"(a[1]), "r"(a[2]), "r"(a[3]), "r"(b[0]), "r"(b[1]));
}

// ============================ graph preprocessing ============================
__global__ void k_zero_deg() {
    int i = blockIdx.x * blockDim.x + threadIdx.x;
    if (i < NN) g_deg[i] = 0;
}
__global__ void k_count(const int* __restrict__ ei) {
    int e = blockIdx.x * blockDim.x + threadIdx.x;
    if (e < EE) { int d = ei[EE + e]; if ((unsigned)d < NN) atomicAdd(&g_deg[d], 1); }
}
__global__ void k_dinv() {
    int i = blockIdx.x * blockDim.x + threadIdx.x;
    if (i < NN) g_dinv[i] = rsqrtf((float)g_deg[i] + 2.0f);
}
__global__ void k_scan1() {
    __shared__ int sm[SCAN_B];
    int t = threadIdx.x, i = blockIdx.x * SCAN_B + t;
    int v = (i < NN) ? g_deg[i] : 0;
    sm[t] = v; __syncthreads();
    for (int s = 1; s < SCAN_B; s <<= 1) {
        int add = (t >= s) ? sm[t - s] : 0;
        __syncthreads(); sm[t] += add; __syncthreads();
    }
    if (i < NN) g_off[i] = sm[t] - v;
    if (t == SCAN_B - 1) g_bsum[blockIdx.x] = sm[t];
}
__global__ void k_scan2() {
    __shared__ int sm[128];
    int t = threadIdx.x;
    int v = (t < NBLK) ? g_bsum[t] : 0;
    sm[t] = v; __syncthreads();
    for (int s = 1; s < 128; s <<= 1) {
        int add = (t >= s) ? sm[t - s] : 0;
        __syncthreads(); sm[t] += add; __syncthreads();
    }
    if (t < NBLK) g_bsum[t] = sm[t] - v;
}
__global__ void k_scan3() {
    int i = blockIdx.x * blockDim.x + threadIdx.x;
    if (i < NN) { int o = g_off[i] + g_bsum[i / SCAN_B]; g_off[i] = o; g_cur[i] = o; }
}
__global__ void k_fill(const int* __restrict__ ei) {
    int e = blockIdx.x * blockDim.x + threadIdx.x;
    if (e < EE) {
        int s = ei[e], d = ei[EE + e];
        if ((unsigned)s < NN && (unsigned)d < NN) g_src[atomicAdd(&g_cur[d], 1)] = s;
    }
}

// ---------------- CSR gather (warp per dst node, 128 channels) ----------------
template<int LAYER>
__global__ void k_gather(const float* __restrict__ Xin, int coff) {
    constexpr int C = (LAYER == 0) ? DIN : HH;
    const float* X = (LAYER == 0) ? Xin : (const float*)g_h;
    float* OUT = (LAYER == 0) ? g_xagg : g_hagg;
    int w = (blockIdx.x * blockDim.x + threadIdx.x) >> 5;
    int lane = threadIdx.x & 31;
    if (w >= NN) return;
    float dv = g_dinv[w];
    const float* Xc = X + coff + lane * 4;
    float4 acc;
    {
        float4 v = *(const float4*)(Xc + (long)w * C);
        float sc = 2.0f * dv * dv;
        acc.x = v.x * sc; acc.y = v.y * sc; acc.z = v.z * sc; acc.w = v.w * sc;
    }
    int off = g_off[w], dg = g_deg[w];
    int j = 0;
    for (; j + 2 <= dg; j += 2) {
        int s0 = g_src[off + j], s1 = g_src[off + j + 1];
        float c0 = g_dinv[s0] * dv, c1 = g_dinv[s1] * dv;
        float4 v0 = *(const float4*)(Xc + (long)s0 * C);
        float4 v1 = *(const float4*)(Xc + (long)s1 * C);
        acc.x += v0.x * c0 + v1.x * c1; acc.y += v0.y * c0 + v1.y * c1;
        acc.z += v0.z * c0 + v1.z * c1; acc.w += v0.w * c0 + v1.w * c1;
    }
    if (j < dg) {
        int s0 = g_src[off + j];
        float c0 = g_dinv[s0] * dv;
        float4 v0 = *(const float4*)(Xc + (long)s0 * C);
        acc.x += v0.x * c0; acc.y += v0.y * c0; acc.z += v0.z * c0; acc.w += v0.w * c0;
    }
    *(float4*)(OUT + coff + (long)w * C + lane * 4) = acc;
}

// ---------------- weight transpose + bf16 split: out[n][k] = W[k][n] ----------------
__global__ void k_wsplit(const float* __restrict__ W, int K, int N, int KP, int NP,
                         __nv_bfloat16* __restrict__ hi, __nv_bfloat16* __restrict__ lo) {
    int idx = blockIdx.x * blockDim.x + threadIdx.x;
    if (idx >= KP * NP) return;
    int n = idx / KP, k = idx % KP;
    float v = (k < K && n < N) ? W[(long)k * N + n] : 0.f;
    __nv_bfloat16 h = __float2bfloat16_rn(v);
    hi[idx] = h;
    lo[idx] = __float2bfloat16_rn(v - __bfloat162float(h));
}

// ============================ warp-MMA split-bf16 GEMM ============================
// CTA 128 x NT, 256 threads (8 warps, 2x4), warp tile 64 x NT/4, BK=32.
// 3-term split per k16: Ah*Bh + Al*Bh + Ah*Bl  (fp32 accum).
// EPI 0: A=g_xagg K=128, NT=256 -> g_h, ReLU.
// EPI 1: A=g_hagg K=256, NT=256 (grid.y=2) -> out_mr (softplus, ldc=500) + g_p (tanh, ld 512, 0-pad).
// EPI 2: A=g_p K=512, NT=128 -> out_y (ldc=100).
template<int EPI>
__global__ void __launch_bounds__(256)
k_mgemm(const __nv_bfloat16* __restrict__ Whi, const __nv_bfloat16* __restrict__ Wlo,
        const float* __restrict__ bias, float* __restrict__ Cout,
        const float* __restrict__ thrp) {
    constexpr int K_TOT = (EPI == 0) ? 128 : (EPI == 1) ? 256 : 512;
    constexpr int NT    = (EPI == 2) ? 128 : 256;
    constexpr int NTW   = NT / 4;       // warp col span
    constexpr int NF    = NTW / 8;      // n-frags per warp (8 or 4)
    constexpr int Nreal = (EPI == 0) ? HH : (EPI == 1) ? MM : OO;
    constexpr int SAB   = 80;           // smem row stride in BYTES (40 bf16) — bank-conflict-free
    constexpr int ABYTES = 128 * SAB;   // 10240
    constexpr int BBYTES = NT * SAB;
    constexpr int OFF_AH = 0, OFF_AL = ABYTES, OFF_BH = 2 * ABYTES, OFF_BL = 2 * ABYTES + BBYTES;
    const float* Asrc = (EPI == 0) ? g_xagg : (EPI == 1) ? g_hagg : g_p;

    extern __shared__ char sm[];
    int tid = threadIdx.x, wid = tid >> 5, lane = tid & 31;
    int group = lane >> 2, tid4 = lane & 3;
    int wm = wid >> 2, wn = wid & 3;
    int rowBlk = blockIdx.x * 128, colBlk = blockIdx.y * NT;
    int WR = wm * 64, WC = wn * NTW;

    float acc[4][NF][4];
#pragma unroll
    for (int mi = 0; mi < 4; mi++)
#pragma unroll
        for (int ni = 0; ni < NF; ni++)
#pragma unroll
            for (int q = 0; q < 4; q++) acc[mi][ni][q] = 0.f;

    uint32_t a_off[4], b_off[NF];
#pragma unroll
    for (int mi = 0; mi < 4; mi++) a_off[mi] = (uint32_t)(WR + mi * 16 + group) * SAB + tid4 * 4;
#pragma unroll
    for (int ni = 0; ni < NF; ni++) b_off[ni] = (uint32_t)(WC + ni * 8 + group) * SAB + tid4 * 4;

    for (int kb = 0; kb < K_TOT; kb += 32) {
        // ---- A: load fp32 128x32, split -> bf16 hi/lo smem ----
#pragma unroll
        for (int i = 0; i < 4; i++) {
            int idx = tid + i * 256;          // 0..1023 float4s
            int row = idx >> 3, c4 = idx & 7;
            int m = rowBlk + row;
            float4 v = make_float4(0.f, 0.f, 0.f, 0.f);
            if (m < NN) v = *(const float4*)(Asrc + (size_t)m * K_TOT + kb + c4 * 4);
            uint64_t hp, lp;
            split4(v, hp, lp);
            uint32_t off = (uint32_t)row * SAB + c4 * 8;
            *(uint64_t*)(sm + OFF_AH + off) = hp;
            *(uint64_t*)(sm + OFF_AL + off) = lp;
        }
        // ---- B: copy pre-split bf16 NT x 32 ----
        constexpr int BIT = NT / 64;          // uint4 per thread per buffer
#pragma unroll
        for (int i = 0; i < BIT; i++) {
            int idx = tid + i * 256;          // 0..NT*4-1
            int row = idx >> 2, u = idx & 3;
            size_t g = (size_t)(colBlk + row) * K_TOT + kb + u * 8;
            uint32_t off = (uint32_t)row * SAB + u * 16;
            *(uint4*)(sm + OFF_BH + off) = *(const uint4*)(Whi + g);
            *(uint4*)(sm + OFF_BL + off) = *(const uint4*)(Wlo + g);
        }
        __syncthreads();
        // ---- MMA: two k16 sub-steps x 3 terms ----
#pragma unroll
        for (int s = 0; s < 2; s++) {
            uint32_t aH[4][4], aL[4][4], bb[NF][2];
#pragma unroll
            for (int mi = 0; mi < 4; mi++) {
                uint32_t base = a_off[mi] + s * 32;
                aH[mi][0] = *(const uint32_t*)(sm + OFF_AH + base);
                aH[mi][1] = *(const uint32_t*)(sm + OFF_AH + base + 8 * SAB);
                aH[mi][2] = *(const uint32_t*)(sm + OFF_AH + base + 16);
                aH[mi][3] = *(const uint32_t*)(sm + OFF_AH + base + 8 * SAB + 16);
                aL[mi][0] = *(const uint32_t*)(sm + OFF_AL + base);
                aL[mi][1] = *(const uint32_t*)(sm + OFF_AL + base + 8 * SAB);
                aL[mi][2] = *(const uint32_t*)(sm + OFF_AL + base + 16);
                aL[mi][3] = *(const uint32_t*)(sm + OFF_AL + base + 8 * SAB + 16);
            }
#pragma unroll
            for (int ni = 0; ni < NF; ni++) {
                uint32_t base = b_off[ni] + s * 32;
                bb[ni][0] = *(const uint32_t*)(sm + OFF_BH + base);
                bb[ni][1] = *(const uint32_t*)(sm + OFF_BH + base + 16);
            }
#pragma unroll
            for (int mi = 0; mi < 4; mi++)
#pragma unroll
                for (int ni = 0; ni < NF; ni++) {
                    mma16816(acc[mi][ni], aH[mi], bb[ni]);
                    mma16816(acc[mi][ni], aL[mi], bb[ni]);
                }
#pragma unroll
            for (int ni = 0; ni < NF; ni++) {
                uint32_t base = b_off[ni] + s * 32;
                bb[ni][0] = *(const uint32_t*)(sm + OFF_BL + base);
                bb[ni][1] = *(const uint32_t*)(sm + OFF_BL + base + 16);
            }
#pragma unroll
            for (int mi = 0; mi < 4; mi++)
#pragma unroll
                for (int ni = 0; ni < NF; ni++)
                    mma16816(acc[mi][ni], aH[mi], bb[ni]);
        }
        __syncthreads();
    }

    // ---- epilogue ----
    float t = 1.f;
    if (EPI == 1) {
        float th = *thrp;
        t = th > 0.f ? th + log1pf(expf(-th)) : log1pf(expf(th));
    }
#pragma unroll
    for (int mi = 0; mi < 4; mi++) {
        int r0 = rowBlk + WR + mi * 16 + group;
#pragma unroll
        for (int ni = 0; ni < NF; ni++) {
            int c0 = colBlk + WC + ni * 8 + tid4 * 2;
#pragma unroll
            for (int half = 0; half < 2; half++) {
                int r = r0 + half * 8;
                if (r >= NN) continue;
                float v0 = acc[mi][ni][half * 2 + 0];
                float v1 = acc[mi][ni][half * 2 + 1];
                if (EPI == 0) {
                    float2 o;
                    o.x = fmaxf(v0 + __ldg(bias + c0 + 0), 0.f);
                    o.y = fmaxf(v1 + __ldg(bias + c0 + 1), 0.f);
                    *(float2*)(g_h + (size_t)r * HH + c0) = o;
                } else if (EPI == 1) {
                    float p0 = 0.f, p1 = 0.f;
                    if (c0 + 1 < Nreal) {
                        float z0 = v0 + __ldg(bias + c0);
                        float z1 = v1 + __ldg(bias + c0 + 1);
                        float sp0 = z0 > 0.f ? z0 + log1pf(expf(-z0)) : log1pf(expf(z0));
                        float sp1 = z1 > 0.f ? z1 + log1pf(expf(-z1)) : log1pf(expf(z1));
                        *(float2*)(Cout + (size_t)r * MM + c0) = make_float2(sp0, sp1);
                        p0 = tanhf(t * sp0); p1 = tanhf(t * sp1);
                    }
                    *(float2*)(g_p + (size_t)r * MP + c0) = make_float2(p0, p1);
                } else {
                    if (c0 + 1 < Nreal) {
                        float2 o;
                        o.x = v0 + __ldg(bias + c0);
                        o.y = v1 + __ldg(bias + c0 + 1);
                        *(float2*)(Cout + (size_t)r * OO + c0) = o;
                    }
                }
            }
        }
    }
}

// ============================ host launch ============================
extern "C" void kernel_launch(void* const* d_in, const int* in_sizes, int n_in,
                              void* d_out, int out_size) {
    const float* x    = (const float*)d_in[0];
    const int*   ei   = (const int*)d_in[1];     // int32 (JAX x64 disabled)
    const float* W1   = (const float*)d_in[2];
    const float* b1   = (const float*)d_in[3];
    const float* W2   = (const float*)d_in[4];
    const float* b2   = (const float*)d_in[5];
    const float* Wout = (const float*)d_in[6];
    const float* bout = (const float*)d_in[7];
    const float* thr  = (const float*)d_in[8];
    float* out = (float*)d_out;
    float* out_mr = out;                  // [N, M]
    float* out_y  = out + (long)NN * MM;  // [N, O]

    const int SMEM_L = 2 * 10240 + 2 * (256 * 80);  // 61440 (NT=256)
    const int SMEM_H = 2 * 10240 + 2 * (128 * 80);  // 40960 (NT=128)
    cudaFuncSetAttribute(k_mgemm<0>, cudaFuncAttributeMaxDynamicSharedMemorySize, SMEM_L);
    cudaFuncSetAttribute(k_mgemm<1>, cudaFuncAttributeMaxDynamicSharedMemorySize, SMEM_L);
    cudaFuncSetAttribute(k_mgemm<2>, cudaFuncAttributeMaxDynamicSharedMemorySize, SMEM_H);

    // graph preprocessing: degrees, dinv, CSR
    k_zero_deg<<<(NN + 255) / 256, 256>>>();
    k_count<<<(EE + 255) / 256, 256>>>(ei);
    k_dinv<<<(NN + 255) / 256, 256>>>();
    k_scan1<<<NBLK, SCAN_B>>>();
    k_scan2<<<1, 128>>>();
    k_scan3<<<(NN + 255) / 256, 256>>>();
    k_fill<<<(EE + 255) / 256, 256>>>(ei);

    // weight transpose + split (small)
    k_wsplit<<<(HH * DIN + 255) / 256, 256>>>(W1, DIN, HH, DIN, HH, g_w1t_hi, g_w1t_lo);
    k_wsplit<<<(MP * HH + 255) / 256, 256>>>(W2, HH, MM, HH, MP, g_w2t_hi, g_w2t_lo);
    k_wsplit<<<(128 * MP + 255) / 256, 256>>>(Wout, MM, OO, MP, 128, g_wot_hi, g_wot_lo);

    int gatherBlocks = (NN * 32 + 255) / 256;   // warp per node
    int rowBlks = (NN + 127) / 128;             // 782

    // layer 1
    k_gather<0><<<gatherBlocks, 256>>>(x, 0);
    k_mgemm<0><<<dim3(rowBlks, 1), 256, SMEM_L>>>(g_w1t_hi, g_w1t_lo, b1, nullptr, nullptr);

    // layer 2 (gather in two channel-half passes for L2 residency)
    k_gather<1><<<gatherBlocks, 256>>>(nullptr, 0);
    k_gather<1><<<gatherBlocks, 256>>>(nullptr, 128);
    k_mgemm<1><<<dim3(rowBlks, 2), 256, SMEM_L>>>(g_w2t_hi, g_w2t_lo, b2, out_mr, thr);

    // output head
    k_mgemm<2><<<dim3(rowBlks, 1), 256, SMEM_H>>>(g_wot_hi, g_wot_lo, bout, out_y, nullptr);
}

// round 9
// speedup vs baseline: 2.4964x; 2.4964x over previous
#include <cuda_runtime.h>
#include <cstdint>

// Problem constants: N=100000, E=3200000, DIN=128, H=256, M=500, O=100
#define NN  100000
#define EE  3200000
#define DIN 128
#define HH  256
#define MM  500
#define MP  512
#define OO  100

#define SCAN_B 1024
#define NBLK ((NN + SCAN_B - 1) / SCAN_B)   // 98

// ---- scratch (static device globals; referenced ONLY from device code) ----
__device__ int   g_deg[NN];
__device__ int   g_off[NN];
__device__ int   g_cur[NN];
__device__ int   g_bsum[128];
__device__ int   g_src[EE];
__device__ float g_dinv[NN];
__device__ __align__(16) float g_xagg[NN * DIN];   // 51.2 MB
__device__ __align__(16) float g_h   [NN * HH];    // 102.4 MB
__device__ __align__(16) float g_hagg[NN * HH];    // 102.4 MB
__device__ __align__(16) float g_p   [NN * MP];    // 204.8 MB

// ============================ helpers ============================
__device__ __forceinline__ void fma2(unsigned long long& d, unsigned long long a, unsigned long long b) {
    asm("fma.rn.f32x2 %0, %1, %2, %0;" : "+l"(d) : "l"(a), "l"(b));
}
__device__ __forceinline__ void unpack2(unsigned long long v, float& lo, float& hi) {
    uint32_t l, h;
    asm("mov.b64 {%0, %1}, %2;" : "=r"(l), "=r"(h) : "l"(v));
    lo = __uint_as_float(l); hi = __uint_as_float(h);
}
__device__ __forceinline__ float softplus_f(float z) {
    // stable: max(z,0) + log(1 + exp(-|z|)), fast intrinsics (rel err ~1e-6)
    float e = __expf(-fabsf(z));
    return fmaxf(z, 0.f) + __logf(1.f + e);
}
__device__ __forceinline__ float tanh_f(float x) {
    // used with x >= 0 (softplus output scaled by positive t)
    float e = __expf(-2.f * x);
    return (1.f - e) / (1.f + e);
}

// ============================ graph preprocessing ============================
__global__ void k_zero_deg() {
    int i = blockIdx.x * blockDim.x + threadIdx.x;
    if (i < NN) g_deg[i] = 0;
}
__global__ void k_count(const int* __restrict__ ei) {
    int e = blockIdx.x * blockDim.x + threadIdx.x;
    if (e < EE) { int d = ei[EE + e]; if ((unsigned)d < NN) atomicAdd(&g_deg[d], 1); }
}
__global__ void k_dinv() {
    int i = blockIdx.x * blockDim.x + threadIdx.x;
    if (i < NN) g_dinv[i] = rsqrtf((float)g_deg[i] + 2.0f);
}
__global__ void k_scan1() {
    __shared__ int sm[SCAN_B];
    int t = threadIdx.x, i = blockIdx.x * SCAN_B + t;
    int v = (i < NN) ? g_deg[i] : 0;
    sm[t] = v; __syncthreads();
    for (int s = 1; s < SCAN_B; s <<= 1) {
        int add = (t >= s) ? sm[t - s] : 0;
        __syncthreads(); sm[t] += add; __syncthreads();
    }
    if (i < NN) g_off[i] = sm[t] - v;
    if (t == SCAN_B - 1) g_bsum[blockIdx.x] = sm[t];
}
__global__ void k_scan2() {
    __shared__ int sm[128];
    int t = threadIdx.x;
    int v = (t < NBLK) ? g_bsum[t] : 0;
    sm[t] = v; __syncthreads();
    for (int s = 1; s < 128; s <<= 1) {
        int add = (t >= s) ? sm[t - s] : 0;
        __syncthreads(); sm[t] += add; __syncthreads();
    }
    if (t < NBLK) g_bsum[t] = sm[t] - v;
}
__global__ void k_scan3() {
    int i = blockIdx.x * blockDim.x + threadIdx.x;
    if (i < NN) { int o = g_off[i] + g_bsum[i / SCAN_B]; g_off[i] = o; g_cur[i] = o; }
}
__global__ void k_fill(const int* __restrict__ ei) {
    int e = blockIdx.x * blockDim.x + threadIdx.x;
    if (e < EE) {
        int s = ei[e], d = ei[EE + e];
        if ((unsigned)s < NN && (unsigned)d < NN) g_src[atomicAdd(&g_cur[d], 1)] = s;
    }
}

// ---------------- CSR gather (warp per dst node, 128 channels) ----------------
template<int LAYER>
__global__ void k_gather(const float* __restrict__ Xin, int coff) {
    constexpr int C = (LAYER == 0) ? DIN : HH;
    const float* X = (LAYER == 0) ? Xin : (const float*)g_h;
    float* OUT = (LAYER == 0) ? g_xagg : g_hagg;
    int w = (blockIdx.x * blockDim.x + threadIdx.x) >> 5;
    int lane = threadIdx.x & 31;
    if (w >= NN) return;
    float dv = g_dinv[w];
    const float* Xc = X + coff + lane * 4;
    float4 acc;
    {
        float4 v = *(const float4*)(Xc + (long)w * C);
        float sc = 2.0f * dv * dv;
        acc.x = v.x * sc; acc.y = v.y * sc; acc.z = v.z * sc; acc.w = v.w * sc;
    }
    int off = g_off[w], dg = g_deg[w];
    int j = 0;
    for (; j + 2 <= dg; j += 2) {
        int s0 = g_src[off + j], s1 = g_src[off + j + 1];
        float c0 = g_dinv[s0] * dv, c1 = g_dinv[s1] * dv;
        float4 v0 = *(const float4*)(Xc + (long)s0 * C);
        float4 v1 = *(const float4*)(Xc + (long)s1 * C);
        acc.x += v0.x * c0 + v1.x * c1; acc.y += v0.y * c0 + v1.y * c1;
        acc.z += v0.z * c0 + v1.z * c1; acc.w += v0.w * c0 + v1.w * c1;
    }
    if (j < dg) {
        int s0 = g_src[off + j];
        float c0 = g_dinv[s0] * dv;
        float4 v0 = *(const float4*)(Xc + (long)s0 * C);
        acc.x += v0.x * c0; acc.y += v0.y * c0; acc.z += v0.z * c0; acc.w += v0.w * c0;
    }
    *(float4*)(OUT + coff + (long)w * C + lane * 4) = acc;
}

// ---------------- packed-f32x2 SGEMM: C = epi(A @ B + bias) ----------------
// BM=128, BN=128, BK=8, 256 threads, 8x8 micro-tile (accumulated as 8x4 f32x2 pairs).
// A stored DUPLICATED in smem: AsD[k][2m] = AsD[k][2m+1] = A[m][k]  (broadcast pairs).
// B pairs taken from contiguous Bs columns.
// EPI 0: A=g_xagg K=128 -> g_h, ReLU.
// EPI 1: A=g_hagg K=256 -> out_mr (softplus) + g_p = tanh(t*softplus) (ld MP, 0-pad).
// EPI 2: A=g_p K=512 (KB=500 guard on B) -> out_y.
template<int EPI>
__global__ void __launch_bounds__(256)
k_gemm(const float* __restrict__ B,
       const float* __restrict__ bias, float* __restrict__ Cout,
       const float* __restrict__ thrp) {
    constexpr int K     = (EPI == 0) ? DIN : (EPI == 1) ? HH : MP;
    constexpr int KB    = (EPI == 2) ? MM : K;
    constexpr int Nreal = (EPI == 0) ? HH : (EPI == 1) ? MM : OO;
    constexpr int ldc   = Nreal;
    const float* A = (EPI == 0) ? g_xagg : (EPI == 1) ? g_hagg : g_p;
    float* C = (EPI == 0) ? g_h : Cout;

    const int BM = 128, BN = 128, BK = 8;
    const int ASTR = 2 * BM + 4;                  // 260 floats (1040B, 16B-aligned rows)
    __shared__ float AsD[BK][ASTR];
    __shared__ float Bs[BK][BN + 4];
    int tid = threadIdx.x;
    int tx = tid & 15;    // col group (x8 -> 4 pairs)
    int ty = tid >> 4;    // row group (x8)
    int rowBlk = blockIdx.y * BM;
    int colBlk = blockIdx.x * BN;

    unsigned long long acc[8][4];
#pragma unroll
    for (int i = 0; i < 8; i++)
#pragma unroll
        for (int j = 0; j < 4; j++) acc[i][j] = 0ull;

    for (int kb = 0; kb < K; kb += BK) {
        // A tile: 128 rows x 8 k, duplicated transposed store
        {
            int row = tid >> 1, part = tid & 1;
            int gr = rowBlk + row;
            float4 v = make_float4(0.f, 0.f, 0.f, 0.f);
            if (gr < NN) v = *(const float4*)(A + (long)gr * K + kb + part * 4);
            *(float2*)&AsD[part * 4 + 0][2 * row] = make_float2(v.x, v.x);
            *(float2*)&AsD[part * 4 + 1][2 * row] = make_float2(v.y, v.y);
            *(float2*)&AsD[part * 4 + 2][2 * row] = make_float2(v.z, v.z);
            *(float2*)&AsD[part * 4 + 3][2 * row] = make_float2(v.w, v.w);
        }
        // B tile: 8 k x 128 n
        {
            int kk = tid >> 5, n4 = tid & 31;
            int gk = kb + kk, gn = colBlk + n4 * 4;
            float4 v = make_float4(0.f, 0.f, 0.f, 0.f);
            if (gk < KB) {
                if (gn + 3 < Nreal) {
                    v = *(const float4*)(B + (long)gk * Nreal + gn);
                } else {
                    if (gn + 0 < Nreal) v.x = B[(long)gk * Nreal + gn + 0];
                    if (gn + 1 < Nreal) v.y = B[(long)gk * Nreal + gn + 1];
                    if (gn + 2 < Nreal) v.z = B[(long)gk * Nreal + gn + 2];
                    if (gn + 3 < Nreal) v.w = B[(long)gk * Nreal + gn + 3];
                }
            }
            *(float4*)&Bs[kk][n4 * 4] = v;
        }
        __syncthreads();
#pragma unroll
        for (int k = 0; k < BK; k++) {
            ulonglong2 a01 = *(const ulonglong2*)&AsD[k][16 * ty + 0];
            ulonglong2 a23 = *(const ulonglong2*)&AsD[k][16 * ty + 4];
            ulonglong2 a45 = *(const ulonglong2*)&AsD[k][16 * ty + 8];
            ulonglong2 a67 = *(const ulonglong2*)&AsD[k][16 * ty + 12];
            ulonglong2 b01 = *(const ulonglong2*)&Bs[k][tx * 8];
            ulonglong2 b23 = *(const ulonglong2*)&Bs[k][tx * 8 + 4];
            unsigned long long ap[8] = {a01.x, a01.y, a23.x, a23.y, a45.x, a45.y, a67.x, a67.y};
            unsigned long long bp[4] = {b01.x, b01.y, b23.x, b23.y};
#pragma unroll
            for (int i = 0; i < 8; i++)
#pragma unroll
                for (int j = 0; j < 4; j++) fma2(acc[i][j], ap[i], bp[j]);
        }
        __syncthreads();
    }

    float t = 1.f;
    if (EPI == 1) t = softplus_f(*thrp);
#pragma unroll
    for (int i = 0; i < 8; i++) {
        int gr = rowBlk + ty * 8 + i;
        if (gr >= NN) continue;
#pragma unroll
        for (int j = 0; j < 4; j++) {
            int gn = colBlk + tx * 8 + j * 2;
            float z0, z1;
            unpack2(acc[i][j], z0, z1);
            if (EPI == 0) {
                float2 o;
                o.x = fmaxf(z0 + bias[gn + 0], 0.f);
                o.y = fmaxf(z1 + bias[gn + 1], 0.f);
                *(float2*)(C + (long)gr * ldc + gn) = o;
            } else if (EPI == 1) {
                float2 p = make_float2(0.f, 0.f);
                if (gn < Nreal) {   // pairs never straddle 500 (even boundary)
                    float sp0 = softplus_f(z0 + bias[gn + 0]);
                    float sp1 = softplus_f(z1 + bias[gn + 1]);
                    *(float2*)(C + (long)gr * ldc + gn) = make_float2(sp0, sp1);
                    p.x = tanh_f(t * sp0); p.y = tanh_f(t * sp1);
                }
                *(float2*)(g_p + (long)gr * MP + gn) = p;   // zero-pad cols [500,512)
            } else {
                if (gn < Nreal) {   // pairs never straddle 100
                    float2 o;
                    o.x = z0 + bias[gn + 0];
                    o.y = z1 + bias[gn + 1];
                    *(float2*)(C + (long)gr * ldc + gn) = o;
                }
            }
        }
    }
}

// ============================ host launch ============================
extern "C" void kernel_launch(void* const* d_in, const int* in_sizes, int n_in,
                              void* d_out, int out_size) {
    const float* x    = (const float*)d_in[0];
    const int*   ei   = (const int*)d_in[1];     // int32 (JAX x64 disabled)
    const float* W1   = (const float*)d_in[2];
    const float* b1   = (const float*)d_in[3];
    const float* W2   = (const float*)d_in[4];
    const float* b2   = (const float*)d_in[5];
    const float* Wout = (const float*)d_in[6];
    const float* bout = (const float*)d_in[7];
    const float* thr  = (const float*)d_in[8];
    float* out = (float*)d_out;
    float* out_mr = out;                  // [N, M]
    float* out_y  = out + (long)NN * MM;  // [N, O]

    // graph preprocessing: degrees, dinv, CSR
    k_zero_deg<<<(NN + 255) / 256, 256>>>();
    k_count<<<(EE + 255) / 256, 256>>>(ei);
    k_dinv<<<(NN + 255) / 256, 256>>>();
    k_scan1<<<NBLK, SCAN_B>>>();
    k_scan2<<<1, 128>>>();
    k_scan3<<<(NN + 255) / 256, 256>>>();
    k_fill<<<(EE + 255) / 256, 256>>>(ei);

    int gatherBlocks = (NN * 32 + 255) / 256;   // warp per node
    int rowBlks = (NN + 127) / 128;             // 782

    // layer 1: xagg = self + A_norm x ; h = relu(xagg@W1 + b1)
    k_gather<0><<<gatherBlocks, 256>>>(x, 0);
    k_gemm<0><<<dim3(HH / 128, rowBlks), 256>>>(W1, b1, nullptr, nullptr);

    // layer 2: hagg = self + A_norm h (two channel-half passes for L2 residency)
    k_gather<1><<<gatherBlocks, 256>>>(nullptr, 0);
    k_gather<1><<<gatherBlocks, 256>>>(nullptr, 128);
    k_gemm<1><<<dim3(MP / 128, rowBlks), 256>>>(W2, b2, out_mr, thr);

    // head: y = p @ Wout + bout  (K padded to 512, B guarded at 500)
    k_gemm<2><<<dim3(1, rowBlks), 256>>>(Wout, bout, out_y, nullptr);
}